// round 8
// baseline (speedup 1.0000x reference)
#include <cuda_runtime.h>

#define SEQ    4096
#define BATCH  4
#define NLW    50
#define HALO   26
#define TILE   32
#define SPLIT  8
#define SPOS   (TILE + 2*HALO)    // 84
#define NS     449
#define NPAIR  230
#define EMAX   354                // max D entries per pair-half
#define OUTL   (SEQ - 2*NLW)      // 3996
#define NBS    (BATCH * SEQ)

typedef unsigned long long u64;

// ---------------- packed f32x2 helpers ----------------
__device__ __forceinline__ u64 fma2(u64 a, u64 b, u64 c) {
    u64 d; asm("fma.rn.f32x2 %0, %1, %2, %3;" : "=l"(d) : "l"(a), "l"(b), "l"(c)); return d;
}
__device__ __forceinline__ u64 mul2(u64 a, u64 b) {
    u64 d; asm("mul.rn.f32x2 %0, %1, %2;" : "=l"(d) : "l"(a), "l"(b)); return d;
}
__device__ __forceinline__ u64 sub2(u64 a, u64 b) {
    u64 d; asm("sub.rn.f32x2 %0, %1, %2;" : "=l"(d) : "l"(a), "l"(b)); return d;
}
__device__ __forceinline__ u64 add2(u64 a, u64 b) {
    u64 d; asm("add.rn.f32x2 %0, %1, %2;" : "=l"(d) : "l"(a), "l"(b)); return d;
}
__device__ __forceinline__ u64 packf2(float2 v) {
    u64 d; asm("mov.b64 %0, {%1, %2};" : "=l"(d) : "f"(v.x), "f"(v.y)); return d;
}
__device__ __forceinline__ u64 pack2(float x) {
    u64 d; asm("mov.b64 %0, {%1, %1};" : "=l"(d) : "f"(x)); return d;
}
__device__ __forceinline__ float2 unpackf2(u64 v) {
    float2 f; asm("mov.b64 {%0, %1}, %2;" : "=f"(f.x), "=f"(f.y) : "l"(v)); return f;
}
__device__ __forceinline__ ulonglong2 cmulconj(ulonglong2 a, ulonglong2 b) {
    ulonglong2 r;
    r.x = fma2(a.y, b.y, mul2(a.x, b.x));
    r.y = sub2(mul2(a.y, b.x), mul2(a.x, b.y));
    return r;
}

// ---------------- compile-time pair schedule, split into 2 halves ----------------
struct PTab {
    int S0f[52]; int NMf[51];
    int RM[21]; int RN0[21]; int RP0[22];
    unsigned char RG[21];          // group (0..10, m=g-5) per run
    short PS1[NPAIR]; short PS2[NPAIR];
    int HP0[2], HP1[2];            // pair range per half
    int HR0[2], HR1[2];            // run range per half
    int DBH[2][12]; int EH[2];     // per-half D layout
    int RDSH[21];                  // per-run local D base (within its half)
    int CBH[2][SPLIT + 1];         // warp chunk boundaries per half
    int CRIH[2][SPLIT];            // starting run per chunk
    unsigned char EGRH[2][EMAX];   // entry -> group per half
    constexpr PTab() : S0f(), NMf(), RM(), RN0(), RP0(), RG(), PS1(), PS2(),
                       HP0(), HP1(), HR0(), HR1(), DBH(), EH(), RDSH(), CBH(), CRIH(), EGRH() {
        int s = 0;
        for (int mi = 0; mi < 51; ++mi) {
            int m = mi - 25, nm = 0;
            for (int n = 1; n <= 25; ++n) { int pp = m * n; if (pp < 0) pp = -pp; if (pp <= 25) nm = n; }
            if (m == 0) nm = 25;
            S0f[mi] = s; NMf[mi] = nm; s += 2 * nm + 1;
        }
        S0f[51] = s;  // 449
        int p = 0, r = 0;
        for (int g = 0; g < 11; ++g) {
            int m = g - 5, am = m < 0 ? -m : m, K = NMf[m + 25];
            int lo1 = (m >= 0) ? m : (am + 1);
            if (K >= lo1) {
                RM[r] = m; RN0[r] = K; RP0[r] = p; RG[r] = (unsigned char)g;
                for (int n = K; n >= lo1; --n) {
                    PS1[p] = (short)(S0f[m + 25] + (n + NMf[m + 25]));
                    PS2[p] = (short)((n == m) ? -1 : (S0f[n + 25] + (m + NMf[n + 25])));
                    ++p;
                }
                ++r;
            }
            int hi2 = (m > 0) ? -m : ((m == 0) ? -1 : -am);
            if (hi2 >= -K) {
                RM[r] = m; RN0[r] = hi2; RP0[r] = p; RG[r] = (unsigned char)g;
                for (int n = hi2; n >= -K; --n) {
                    PS1[p] = (short)(S0f[m + 25] + (n + NMf[m + 25]));
                    PS2[p] = (short)((n == m) ? -1 : (S0f[n + 25] + (m + NMf[n + 25])));
                    ++p;
                }
                ++r;
            }
        }
        RP0[21] = p;   // 230
        // halves: split at run 10 (pairs 0..112 / 113..229)
        HR0[0] = 0;  HR1[0] = 10; HP0[0] = 0;       HP1[0] = RP0[10];
        HR0[1] = 10; HR1[1] = 21; HP0[1] = RP0[10]; HP1[1] = NPAIR;
        for (int h = 0; h < 2; ++h) {
            int gs = RG[HR0[h]], ge = RG[HR1[h] - 1];
            int acc = 0;
            for (int g = gs; g <= ge; ++g) {
                DBH[h][g] = acc;
                acc += TILE + 2 * NMf[(g - 5) + 25];
            }
            EH[h] = acc;
            int e = 0;
            for (int g = gs; g <= ge; ++g) {
                int len = TILE + 2 * NMf[(g - 5) + 25];
                for (int k = 0; k < len; ++k) EGRH[h][e++] = (unsigned char)g;
            }
            for (int ri = HR0[h]; ri < HR1[h]; ++ri) {
                int g = RG[ri];
                RDSH[ri] = DBH[h][g] + NMf[(g - 5) + 25] - RN0[ri];
            }
            for (int t = 0; t <= SPLIT; ++t)
                CBH[h][t] = HP0[h] + (HP1[h] - HP0[h]) * t / SPLIT;
            for (int t = 0; t < SPLIT; ++t) {
                int k = HR0[h];
                while (RP0[k + 1] <= CBH[h][t]) ++k;
                CRIH[h][t] = k;
            }
        }
    }
};
__constant__ PTab c_pt = PTab();

struct __align__(16) WR { ulonglong2 a, b; };

// per-half raw partial sums (unscaled), packed mode-pairs
__device__ u64 g_E1r[2 * NBS];
__device__ u64 g_E1i[2 * NBS];
__device__ u64 g_Mr [2 * NBS];
__device__ u64 g_Mi [2 * NBS];
__device__ u64 g_Fr [2 * NBS];
__device__ u64 g_Fi [2 * NBS];

// ---------------------------------------------------------------------------
// Stage 1 (per pair-half): raw partial sums of E1, M
// ---------------------------------------------------------------------------
__global__ void __launch_bounds__(TILE * SPLIT, 5)
stage1_kernel(const float2* __restrict__ Er, const float2* __restrict__ Ei,
              const float*  __restrict__ w1r, const float* __restrict__ w1i,
              const float*  __restrict__ w2r, const float* __restrict__ w2i)
{
    __shared__ ulonglong2 sE[SPOS];
    __shared__ ulonglong2 sD[EMAX];
    __shared__ WR sW[NPAIR];
    __shared__ ulonglong2 sR1[SPLIT - 1][TILE];
    __shared__ ulonglong2 sR2[SPLIT - 1][TILE];

    const int tile = blockIdx.x, b = blockIdx.y, ph = blockIdx.z;
    const int tx = threadIdx.x, ty = threadIdx.y;
    const int tid = ty * TILE + tx;
    const int base = tile * TILE;
    const float2* Erb = Er + b * SEQ;
    const float2* Eib = Ei + b * SEQ;

    for (int i = tid; i < SPOS; i += TILE * SPLIT) {
        int pp = (base - HALO + i) & (SEQ - 1);
        sE[i] = make_ulonglong2(packf2(Erb[pp]), packf2(Eib[pp]));
    }
    for (int p0 = tid + c_pt.HP0[ph]; p0 < c_pt.HP1[ph]; p0 += TILE * SPLIT) {
        const int s1 = c_pt.PS1[p0], s2 = c_pt.PS2[p0];
        float ar = w1r[s1], ai = w1i[s1];
        float br = w2r[s1], bi = w2i[s1];
        if (s2 >= 0) { ar += w1r[s2]; ai += w1i[s2]; br += w2r[s2]; bi += w2i[s2]; }
        WR w;
        w.a = make_ulonglong2(pack2(ar), pack2(ai));
        w.b = make_ulonglong2(pack2(br), pack2(bi));
        sW[p0] = w;
    }
    __syncthreads();

    for (int e = tid; e < c_pt.EH[ph]; e += TILE * SPLIT) {
        const int g = c_pt.EGRH[ph][e];
        const int t = e - c_pt.DBH[ph][g];
        const int m = g - 5;
        const int nm = c_pt.NMf[m + 25];
        const int jE = t + HALO - nm;
        sD[e] = cmulconj(sE[jE], sE[jE - m]);
    }
    __syncthreads();

    const int li = tx + HALO;
    const u64 z = 0;
    u64 e1r = 0, e1i = 0, mr = 0, mi_ = 0;

    int p = c_pt.CBH[ph][ty];
    const int pEnd = c_pt.CBH[ph][ty + 1];
    int r = c_pt.CRIH[ph][ty];
    while (p < pEnd) {
        const int m = c_pt.RM[r];
        const int rEnd = min(c_pt.RP0[r + 1], pEnd);
        const ulonglong2 av = sE[li - m];
        int idx = c_pt.RDSH[r] + (p - c_pt.RP0[r]) + tx;
        u64 y1ra = 0, y1rb = 0, y1ia = 0, y1ib = 0;
        u64 y2ra = 0, y2rb = 0, y2ia = 0, y2ib = 0;
        #pragma unroll 2
        for (; p < rEnd; ++p, ++idx) {
            const ulonglong2 Dv = sD[idx];
            const WR w = sW[p];
            y1ra = fma2(w.a.x, Dv.x, y1ra);  y1rb = fma2(w.a.y, Dv.y, y1rb);
            y1ia = fma2(w.a.x, Dv.y, y1ia);  y1ib = fma2(w.a.y, Dv.x, y1ib);
            y2ra = fma2(w.b.x, Dv.x, y2ra);  y2rb = fma2(w.b.y, Dv.y, y2rb);
            y2ia = fma2(w.b.x, Dv.y, y2ia);  y2ib = fma2(w.b.y, Dv.x, y2ib);
        }
        const u64 y1r = sub2(y1ra, y1rb), y1i = add2(y1ia, y1ib);
        const u64 y2r = sub2(y2ra, y2rb), y2i = add2(y2ia, y2ib);
        const u64 nav = sub2(z, av.y);
        e1r = fma2(av.x, y1r, fma2(nav,  y1i, e1r));
        e1i = fma2(av.x, y1i, fma2(av.y, y1r, e1i));
        mr  = fma2(av.x, y2r, fma2(nav,  y2i, mr));
        mi_ = fma2(av.x, y2i, fma2(av.y, y2r, mi_));
        ++r;
    }

    if (ty > 0) {
        sR1[ty - 1][tx] = make_ulonglong2(e1r, e1i);
        sR2[ty - 1][tx] = make_ulonglong2(mr, mi_);
    }
    __syncthreads();
    if (ty == 0) {
        #pragma unroll
        for (int j = 0; j < SPLIT - 1; ++j) {
            const ulonglong2 r1 = sR1[j][tx], r2 = sR2[j][tx];
            e1r = add2(e1r, r1.x);  e1i = add2(e1i, r1.y);
            mr  = add2(mr,  r2.x);  mi_ = add2(mi_, r2.y);
        }
        const int gi = ph * NBS + b * SEQ + base + tx;
        g_E1r[gi] = e1r;
        g_E1i[gi] = e1i;
        g_Mr [gi] = mr;
        g_Mi [gi] = mi_;
    }
}

// ---------------------------------------------------------------------------
// Stage 2 (per pair-half): raw partial F
// ---------------------------------------------------------------------------
__global__ void __launch_bounds__(TILE * SPLIT, 5)
stage2_kernel(const float2* __restrict__ Er, const float2* __restrict__ Ei,
              const float*  __restrict__ task,
              const float*  __restrict__ fcr, const float* __restrict__ fci)
{
    __shared__ ulonglong2 sE[SPOS];
    __shared__ ulonglong2 sM[SPOS];
    __shared__ ulonglong2 sD[EMAX];
    __shared__ ulonglong2 sGE[EMAX];
    __shared__ ulonglong2 sEG[EMAX];
    __shared__ WR sWab[NPAIR];
    __shared__ ulonglong2 sWc[NPAIR];
    __shared__ ulonglong2 sR[SPLIT - 1][TILE];

    const int tile = blockIdx.x, b = blockIdx.y, ph = blockIdx.z;
    const int tx = threadIdx.x, ty = threadIdx.y;
    const int tid = ty * TILE + tx;
    const int base = tile * TILE;
    const float2* Erb = Er + b * SEQ;
    const float2* Eib = Ei + b * SEQ;
    const u64 Ps = pack2(exp10f(task[b * 4] * 0.1f) * 0.5f);

    for (int i = tid; i < SPOS; i += TILE * SPLIT) {
        int pp = (base - HALO + i) & (SEQ - 1);
        int gp = b * SEQ + pp;
        sE[i] = make_ulonglong2(packf2(Erb[pp]), packf2(Eib[pp]));
        sM[i] = make_ulonglong2(mul2(add2(g_Mr[gp], g_Mr[NBS + gp]), Ps),
                                mul2(add2(g_Mi[gp], g_Mi[NBS + gp]), Ps));
    }
    for (int p0 = tid + c_pt.HP0[ph]; p0 < c_pt.HP1[ph]; p0 += TILE * SPLIT) {
        const int s1 = c_pt.PS1[p0], s2 = c_pt.PS2[p0];
        const float a_r = fcr[s1], a_i = fci[s1];
        float b_r = 0.f, b_i = 0.f;
        float cR = fcr[NS + s1], cI = fci[NS + s1];
        if (s2 >= 0) { b_r = fcr[s2]; b_i = fci[s2]; cR += fcr[NS + s2]; cI += fci[NS + s2]; }
        WR w;
        w.a = make_ulonglong2(pack2(a_r), pack2(a_i));
        w.b = make_ulonglong2(pack2(b_r), pack2(b_i));
        sWab[p0] = w;
        sWc[p0] = make_ulonglong2(pack2(cR), pack2(cI));
    }
    __syncthreads();

    for (int e = tid; e < c_pt.EH[ph]; e += TILE * SPLIT) {
        const int g = c_pt.EGRH[ph][e];
        const int t = e - c_pt.DBH[ph][g];
        const int m = g - 5;
        const int nm = c_pt.NMf[m + 25];
        const int jE = t + HALO - nm;
        const ulonglong2 Ej  = sE[jE];
        const ulonglong2 Ejm = sE[jE - m];
        const ulonglong2 Gj  = sM[jE];
        const ulonglong2 Gjm = sM[jE - m];
        sD[e]  = cmulconj(Ej, Ejm);
        sGE[e] = cmulconj(Gj, Ejm);
        sEG[e] = cmulconj(Ej, Gjm);
    }
    __syncthreads();

    const int li = tx + HALO;
    const u64 z = 0;
    u64 fr = 0, fi = 0;

    int p = c_pt.CBH[ph][ty];
    const int pEnd = c_pt.CBH[ph][ty + 1];
    int r = c_pt.CRIH[ph][ty];
    while (p < pEnd) {
        const int m = c_pt.RM[r];
        const int rEnd = min(c_pt.RP0[r + 1], pEnd);
        const int lia = li - m;
        const ulonglong2 av = sE[lia];
        const ulonglong2 gv = sM[lia];
        int idx = c_pt.RDSH[r] + (p - c_pt.RP0[r]) + tx;
        u64 y1ra = 0, y1rb = 0, y1ia = 0, y1ib = 0;
        u64 yara = 0, yarb = 0, yaia = 0, yaib = 0;
        #pragma unroll 1
        for (; p < rEnd; ++p, ++idx) {
            const ulonglong2 Dv  = sD[idx];
            const ulonglong2 GEv = sGE[idx];
            const ulonglong2 EGv = sEG[idx];
            const WR w = sWab[p];
            const ulonglong2 wc = sWc[p];
            y1ra = fma2(w.a.x, Dv.x,  y1ra);  y1rb = fma2(w.a.y, Dv.y,  y1rb);
            y1ia = fma2(w.a.x, Dv.y,  y1ia);  y1ib = fma2(w.a.y, Dv.x,  y1ib);
            yara = fma2(w.b.x, GEv.x, yara);  yarb = fma2(w.b.y, GEv.y, yarb);
            yaia = fma2(w.b.x, GEv.y, yaia);  yaib = fma2(w.b.y, GEv.x, yaib);
            yara = fma2(wc.x,  EGv.x, yara);  yarb = fma2(wc.y,  EGv.y, yarb);
            yaia = fma2(wc.x,  EGv.y, yaia);  yaib = fma2(wc.y,  EGv.x, yaib);
        }
        const u64 y1r = sub2(y1ra, y1rb), y1i = add2(y1ia, y1ib);
        const u64 yar = sub2(yara, yarb), yai = add2(yaia, yaib);
        const u64 ngv = sub2(z, gv.y);
        const u64 nav = sub2(z, av.y);
        fr = fma2(gv.x, y1r, fma2(ngv,  y1i, fr));
        fi = fma2(gv.x, y1i, fma2(gv.y, y1r, fi));
        fr = fma2(av.x, yar, fma2(nav,  yai, fr));
        fi = fma2(av.x, yai, fma2(av.y, yar, fi));
        ++r;
    }

    if (ty > 0)
        sR[ty - 1][tx] = make_ulonglong2(fr, fi);
    __syncthreads();
    if (ty == 0) {
        #pragma unroll
        for (int j = 0; j < SPLIT - 1; ++j) {
            const ulonglong2 rr = sR[j][tx];
            fr = add2(fr, rr.x);  fi = add2(fi, rr.y);
        }
        const int gi = ph * NBS + b * SEQ + base + tx;
        g_Fr[gi] = fr;
        g_Fi[gi] = fi;
    }
}

// ---------------------------------------------------------------------------
// Combine: out = E + 0.1*Ps*(E1p0+E1p1) + 0.01*Ps*(F0+F1), sliced
// ---------------------------------------------------------------------------
__global__ void __launch_bounds__(256)
combine_kernel(const float2* __restrict__ Er, const float2* __restrict__ Ei,
               const float*  __restrict__ task, float4* __restrict__ out)
{
    const int b = blockIdx.y;
    const int l = blockIdx.x * 256 + threadIdx.x + NLW;
    if (l >= SEQ - NLW) return;
    const float Psf = exp10f(task[b * 4] * 0.1f) * 0.5f;
    const u64 c1 = pack2(0.1f * Psf);
    const u64 c2 = pack2(0.01f * Psf);
    const int gi = b * SEQ + l;
    const u64 e1r = add2(g_E1r[gi], g_E1r[NBS + gi]);
    const u64 e1i = add2(g_E1i[gi], g_E1i[NBS + gi]);
    const u64 fr  = add2(g_Fr[gi],  g_Fr[NBS + gi]);
    const u64 fi  = add2(g_Fi[gi],  g_Fi[NBS + gi]);
    const u64 er = packf2(Er[gi]);
    const u64 ei = packf2(Ei[gi]);
    const u64 outr = fma2(c2, fr, fma2(c1, e1r, er));
    const u64 outi = fma2(c2, fi, fma2(c1, e1i, ei));
    const float2 orr = unpackf2(outr);
    const float2 oii = unpackf2(outi);
    out[b * OUTL + (l - NLW)] = make_float4(orr.x, oii.x, orr.y, oii.y);
}

extern "C" void kernel_launch(void* const* d_in, const int* in_sizes, int n_in,
                              void* d_out, int out_size)
{
    const float2* Er   = (const float2*)d_in[0];
    const float2* Ei   = (const float2*)d_in[1];
    const float*  task = (const float*)d_in[2];
    const float*  w1r  = (const float*)d_in[3];
    const float*  w1i  = (const float*)d_in[4];
    const float*  w2r  = (const float*)d_in[5];
    const float*  w2i  = (const float*)d_in[6];
    const float*  fcr  = (const float*)d_in[7];
    const float*  fci  = (const float*)d_in[8];

    dim3 grid(SEQ / TILE, BATCH, 2);
    dim3 blk(TILE, SPLIT);
    stage1_kernel<<<grid, blk>>>(Er, Ei, w1r, w1i, w2r, w2i);
    stage2_kernel<<<grid, blk>>>(Er, Ei, task, fcr, fci);
    dim3 cgrid((OUTL + 255) / 256, BATCH);
    combine_kernel<<<cgrid, 256>>>(Er, Ei, task, (float4*)d_out);
}

// round 10
// speedup vs baseline: 1.2179x; 1.2179x over previous
#include <cuda_runtime.h>

#define SEQ    4096
#define BATCH  4
#define NLW    50
#define HALO   26
#define TILE   32
#define SPLIT  8
#define SPOS   (TILE + 2*HALO)    // 84
#define NS     449
#define NPAIR  230
#define ENT    686                // sum over 11 groups of (TILE + 2*(nm+|m|)), m=0 -> 25
#define OUTL   (SEQ - 2*NLW)      // 3996

typedef unsigned long long u64;

// ---------------- packed f32x2 helpers ----------------
__device__ __forceinline__ u64 fma2(u64 a, u64 b, u64 c) {
    u64 d; asm("fma.rn.f32x2 %0, %1, %2, %3;" : "=l"(d) : "l"(a), "l"(b), "l"(c)); return d;
}
__device__ __forceinline__ u64 mul2(u64 a, u64 b) {
    u64 d; asm("mul.rn.f32x2 %0, %1, %2;" : "=l"(d) : "l"(a), "l"(b)); return d;
}
__device__ __forceinline__ u64 sub2(u64 a, u64 b) {
    u64 d; asm("sub.rn.f32x2 %0, %1, %2;" : "=l"(d) : "l"(a), "l"(b)); return d;
}
__device__ __forceinline__ u64 add2(u64 a, u64 b) {
    u64 d; asm("add.rn.f32x2 %0, %1, %2;" : "=l"(d) : "l"(a), "l"(b)); return d;
}
__device__ __forceinline__ u64 packf2(float2 v) {
    u64 d; asm("mov.b64 %0, {%1, %2};" : "=l"(d) : "f"(v.x), "f"(v.y)); return d;
}
__device__ __forceinline__ u64 pack2(float x) {
    u64 d; asm("mov.b64 %0, {%1, %1};" : "=l"(d) : "f"(x)); return d;
}
__device__ __forceinline__ float2 unpackf2(u64 v) {
    float2 f; asm("mov.b64 {%0, %1}, %2;" : "=f"(f.x), "=f"(f.y) : "l"(v)); return f;
}
__device__ __forceinline__ ulonglong2 cmulconj(ulonglong2 a, ulonglong2 b) {
    ulonglong2 r;
    r.x = fma2(a.y, b.y, mul2(a.x, b.x));
    r.y = sub2(mul2(a.y, b.x), mul2(a.x, b.y));
    return r;
}

// ---------------- compile-time schedule ----------------
// Pair set: unordered {(m,n),(n,m)}, owner groups m in [-5,5], 21 contiguous
// descending-n runs, 230 pairs. D/GE arrays per group with halo Hg = nm+|m|
// (m=0: 25) so EG_m[j] = conj(GE_{-m}[j-m]) reads stay in-array.
struct PTab {
    int S0f[52]; int NMf[51];
    int Hgs[11]; int DB[12];
    int RM[21]; int RN0[21]; int RP0[22];
    int RDS[21];            // idx = RDS[r] + (p - RP0[r]) + tx
    int RDOFF[21];          // mirror-group GE offset: DB[10-g] - DB[g] - m
    short PS1[NPAIR]; short PS2[NPAIR];
    int CB[SPLIT + 1]; int CRI[SPLIT];
    unsigned char EGR[ENT];
    constexpr PTab() : S0f(), NMf(), Hgs(), DB(), RM(), RN0(), RP0(), RDS(), RDOFF(),
                       PS1(), PS2(), CB(), CRI(), EGR() {
        int s = 0;
        for (int mi = 0; mi < 51; ++mi) {
            int m = mi - 25, nm = 0;
            for (int n = 1; n <= 25; ++n) { int pp = m * n; if (pp < 0) pp = -pp; if (pp <= 25) nm = n; }
            if (m == 0) nm = 25;
            S0f[mi] = s; NMf[mi] = nm; s += 2 * nm + 1;
        }
        S0f[51] = s;  // 449
        // group halos + layout
        int acc = 0;
        for (int g = 0; g < 11; ++g) {
            int m = g - 5, am = m < 0 ? -m : m;
            int nm = NMf[m + 25];
            Hgs[g] = (m == 0) ? 25 : (nm + am);
            DB[g] = acc;
            acc += TILE + 2 * Hgs[g];
        }
        DB[11] = acc;   // == ENT
        int e = 0;
        for (int g = 0; g < 11; ++g) {
            int len = TILE + 2 * Hgs[g];
            for (int k = 0; k < len; ++k) EGR[e++] = (unsigned char)g;
        }
        // pair runs
        int p = 0, r = 0;
        for (int g = 0; g < 11; ++g) {
            int m = g - 5, am = m < 0 ? -m : m, K = NMf[m + 25];
            int lo1 = (m >= 0) ? m : (am + 1);
            if (K >= lo1) {
                RM[r] = m; RN0[r] = K; RP0[r] = p;
                RDS[r] = DB[g] + Hgs[g] - K;
                RDOFF[r] = DB[10 - g] - DB[g] - m;
                for (int n = K; n >= lo1; --n) {
                    PS1[p] = (short)(S0f[m + 25] + (n + NMf[m + 25]));
                    PS2[p] = (short)((n == m) ? -1 : (S0f[n + 25] + (m + NMf[n + 25])));
                    ++p;
                }
                ++r;
            }
            int hi2 = (m > 0) ? -m : ((m == 0) ? -1 : -am);
            if (hi2 >= -K) {
                RM[r] = m; RN0[r] = hi2; RP0[r] = p;
                RDS[r] = DB[g] + Hgs[g] - hi2;
                RDOFF[r] = DB[10 - g] - DB[g] - m;
                for (int n = hi2; n >= -K; --n) {
                    PS1[p] = (short)(S0f[m + 25] + (n + NMf[m + 25]));
                    PS2[p] = (short)((n == m) ? -1 : (S0f[n + 25] + (m + NMf[n + 25])));
                    ++p;
                }
                ++r;
            }
        }
        RP0[21] = p;   // 230
        for (int t = 0; t <= SPLIT; ++t) CB[t] = NPAIR * t / SPLIT;
        for (int t = 0; t < SPLIT; ++t) {
            int k = 0;
            while (RP0[k + 1] <= CB[t]) ++k;
            CRI[t] = k;
        }
    }
};
__constant__ PTab c_pt = PTab();

struct __align__(16) WR { ulonglong2 a, b; };

// scratch (Ps-scaled), packed mode-pairs
__device__ u64 g_E1r[BATCH * SEQ];
__device__ u64 g_E1i[BATCH * SEQ];
__device__ u64 g_Mr [BATCH * SEQ];
__device__ u64 g_Mi [BATCH * SEQ];

// ---------------------------------------------------------------------------
// Stage 1:  D_m[j] = E[j]*conj(E[j-m]);  E1[l] = Ps * sum E[l-m] * (w1sym . D),
//           M likewise with w2sym.
// ---------------------------------------------------------------------------
__global__ void __launch_bounds__(TILE * SPLIT, 4)
stage1_kernel(const float2* __restrict__ Er, const float2* __restrict__ Ei,
              const float*  __restrict__ task,
              const float*  __restrict__ w1r, const float* __restrict__ w1i,
              const float*  __restrict__ w2r, const float* __restrict__ w2i)
{
    __shared__ ulonglong2 sE[SPOS];
    __shared__ ulonglong2 sD[ENT];
    __shared__ WR sW[NPAIR];
    __shared__ ulonglong2 sR1[SPLIT - 1][TILE];
    __shared__ ulonglong2 sR2[SPLIT - 1][TILE];

    const int tile = blockIdx.x, b = blockIdx.y;
    const int tx = threadIdx.x, ty = threadIdx.y;
    const int tid = ty * TILE + tx;
    const int base = tile * TILE;
    const float2* Erb = Er + b * SEQ;
    const float2* Eib = Ei + b * SEQ;

    for (int i = tid; i < SPOS; i += TILE * SPLIT) {
        int pp = (base - HALO + i) & (SEQ - 1);
        sE[i] = make_ulonglong2(packf2(Erb[pp]), packf2(Eib[pp]));
    }
    for (int p0 = tid; p0 < NPAIR; p0 += TILE * SPLIT) {
        const int s1 = c_pt.PS1[p0], s2 = c_pt.PS2[p0];
        float ar = w1r[s1], ai = w1i[s1];
        float br = w2r[s1], bi = w2i[s1];
        if (s2 >= 0) { ar += w1r[s2]; ai += w1i[s2]; br += w2r[s2]; bi += w2i[s2]; }
        WR w;
        w.a = make_ulonglong2(pack2(ar), pack2(ai));
        w.b = make_ulonglong2(pack2(br), pack2(bi));
        sW[p0] = w;
    }
    __syncthreads();

    for (int e = tid; e < ENT; e += TILE * SPLIT) {
        const int g = c_pt.EGR[e];
        const int m = g - 5;
        const int jE = e - c_pt.DB[g] + HALO - c_pt.Hgs[g];
        int jm = jE - m;
        jm = jm < 0 ? 0 : (jm > SPOS - 1 ? SPOS - 1 : jm);   // corners never consumed
        sD[e] = cmulconj(sE[jE], sE[jm]);
    }
    __syncthreads();

    const u64 z = 0;
    u64 e1r = 0, e1i = 0, mr = 0, mi_ = 0;

    int p = c_pt.CB[ty];
    const int pEnd = c_pt.CB[ty + 1];
    int r = c_pt.CRI[ty];
    while (p < pEnd) {
        const int m = c_pt.RM[r];
        const int rEnd = min(c_pt.RP0[r + 1], pEnd);
        const ulonglong2 av = sE[tx + HALO - m];
        int idx = c_pt.RDS[r] + (p - c_pt.RP0[r]) + tx;
        u64 y1ra = 0, y1rb = 0, y1ia = 0, y1ib = 0;
        u64 y2ra = 0, y2rb = 0, y2ia = 0, y2ib = 0;
        #pragma unroll 4
        for (; p < rEnd; ++p, ++idx) {
            const ulonglong2 Dv = sD[idx];
            const WR w = sW[p];
            y1ra = fma2(w.a.x, Dv.x, y1ra);  y1rb = fma2(w.a.y, Dv.y, y1rb);
            y1ia = fma2(w.a.x, Dv.y, y1ia);  y1ib = fma2(w.a.y, Dv.x, y1ib);
            y2ra = fma2(w.b.x, Dv.x, y2ra);  y2rb = fma2(w.b.y, Dv.y, y2rb);
            y2ia = fma2(w.b.x, Dv.y, y2ia);  y2ib = fma2(w.b.y, Dv.x, y2ib);
        }
        const u64 y1r = sub2(y1ra, y1rb), y1i = add2(y1ia, y1ib);
        const u64 y2r = sub2(y2ra, y2rb), y2i = add2(y2ia, y2ib);
        const u64 nav = sub2(z, av.y);
        e1r = fma2(av.x, y1r, fma2(nav,  y1i, e1r));
        e1i = fma2(av.x, y1i, fma2(av.y, y1r, e1i));
        mr  = fma2(av.x, y2r, fma2(nav,  y2i, mr));
        mi_ = fma2(av.x, y2i, fma2(av.y, y2r, mi_));
        ++r;
    }

    if (ty > 0) {
        sR1[ty - 1][tx] = make_ulonglong2(e1r, e1i);
        sR2[ty - 1][tx] = make_ulonglong2(mr, mi_);
    }
    __syncthreads();
    if (ty == 0) {
        #pragma unroll
        for (int j = 0; j < SPLIT - 1; ++j) {
            const ulonglong2 r1 = sR1[j][tx], r2 = sR2[j][tx];
            e1r = add2(e1r, r1.x);  e1i = add2(e1i, r1.y);
            mr  = add2(mr,  r2.x);  mi_ = add2(mi_, r2.y);
        }
        const u64 Ps = pack2(exp10f(task[b * 4] * 0.1f) * 0.5f);
        const int gi = b * SEQ + base + tx;
        g_E1r[gi] = mul2(e1r, Ps);
        g_E1i[gi] = mul2(e1i, Ps);
        g_Mr [gi] = mul2(mr,  Ps);
        g_Mi [gi] = mul2(mi_, Ps);
    }
}

// ---------------------------------------------------------------------------
// Stage 2:  GE_m[j] = G[j]*conj(E[j-m]);  EG_m[j] = conj(GE_{-m}[j-m]).
//   F[l] = sum_runs [ G[l-m]*(w1a . D_m) + E[l-m]*(w1b . GE_m + w2s . EG_m) ]
//   out  = E + 0.1*E1 + 0.01*Ps*F,  sliced l in [50, 4046)
// ---------------------------------------------------------------------------
__global__ void __launch_bounds__(TILE * SPLIT, 4)
stage2_kernel(const float2* __restrict__ Er, const float2* __restrict__ Ei,
              const float*  __restrict__ task,
              const float*  __restrict__ fcr, const float* __restrict__ fci,
              float4* __restrict__ out)
{
    __shared__ ulonglong2 sE[SPOS];
    __shared__ ulonglong2 sM[SPOS];
    __shared__ ulonglong2 sD[ENT];
    __shared__ ulonglong2 sGE[ENT];
    __shared__ WR sWab[NPAIR];
    __shared__ ulonglong2 sWc[NPAIR];
    __shared__ ulonglong2 sR[SPLIT - 1][TILE];

    const int tile = blockIdx.x, b = blockIdx.y;
    const int tx = threadIdx.x, ty = threadIdx.y;
    const int tid = ty * TILE + tx;
    const int base = tile * TILE;
    const float2* Erb = Er + b * SEQ;
    const float2* Eib = Ei + b * SEQ;

    for (int i = tid; i < SPOS; i += TILE * SPLIT) {
        int pp = (base - HALO + i) & (SEQ - 1);
        int gp = b * SEQ + pp;
        sE[i] = make_ulonglong2(packf2(Erb[pp]), packf2(Eib[pp]));
        sM[i] = make_ulonglong2(g_Mr[gp], g_Mi[gp]);
    }
    for (int p0 = tid; p0 < NPAIR; p0 += TILE * SPLIT) {
        const int s1 = c_pt.PS1[p0], s2 = c_pt.PS2[p0];
        const float a_r = fcr[s1], a_i = fci[s1];
        float b_r = 0.f, b_i = 0.f;
        float cR = fcr[NS + s1], cI = fci[NS + s1];
        if (s2 >= 0) { b_r = fcr[s2]; b_i = fci[s2]; cR += fcr[NS + s2]; cI += fci[NS + s2]; }
        WR w;
        w.a = make_ulonglong2(pack2(a_r), pack2(a_i));
        w.b = make_ulonglong2(pack2(b_r), pack2(b_i));
        sWab[p0] = w;
        sWc[p0] = make_ulonglong2(pack2(cR), pack2(cI));
    }
    __syncthreads();

    for (int e = tid; e < ENT; e += TILE * SPLIT) {
        const int g = c_pt.EGR[e];
        const int m = g - 5;
        const int jE = e - c_pt.DB[g] + HALO - c_pt.Hgs[g];
        int jm = jE - m;
        jm = jm < 0 ? 0 : (jm > SPOS - 1 ? SPOS - 1 : jm);
        const ulonglong2 Ejm = sE[jm];
        sD[e]  = cmulconj(sE[jE], Ejm);
        sGE[e] = cmulconj(sM[jE], Ejm);
    }
    __syncthreads();

    const u64 z = 0;
    u64 fr = 0, fi = 0;

    int p = c_pt.CB[ty];
    const int pEnd = c_pt.CB[ty + 1];
    int r = c_pt.CRI[ty];
    while (p < pEnd) {
        const int m = c_pt.RM[r];
        const int rEnd = min(c_pt.RP0[r + 1], pEnd);
        const int doff = c_pt.RDOFF[r];
        const int lia = tx + HALO - m;
        const ulonglong2 av = sE[lia];
        const ulonglong2 gv = sM[lia];
        int idx = c_pt.RDS[r] + (p - c_pt.RP0[r]) + tx;
        u64 y1ra = 0, y1rb = 0, y1ia = 0, y1ib = 0;
        u64 yara = 0, yarb = 0, yaia = 0, yaib = 0;
        #pragma unroll 2
        for (; p < rEnd; ++p, ++idx) {
            const ulonglong2 Dv  = sD[idx];
            const ulonglong2 GEv = sGE[idx];
            const ulonglong2 Vv  = sGE[idx + doff];   // EG_m = conj(Vv)
            const WR w = sWab[p];
            const ulonglong2 wc = sWc[p];
            // y1 += wa * D
            y1ra = fma2(w.a.x, Dv.x,  y1ra);  y1rb = fma2(w.a.y, Dv.y,  y1rb);
            y1ia = fma2(w.a.x, Dv.y,  y1ia);  y1ib = fma2(w.a.y, Dv.x,  y1ib);
            // ya += wb*GE + wc*conj(V)
            yara = fma2(w.b.x, GEv.x, yara);  yarb = fma2(w.b.y, GEv.y, yarb);
            yara = fma2(wc.x,  Vv.x,  yara);  yara = fma2(wc.y,  Vv.y,  yara);
            yaia = fma2(w.b.x, GEv.y, yaia);  yaia = fma2(w.b.y, GEv.x, yaia);
            yaia = fma2(wc.y,  Vv.x,  yaia);  yaib = fma2(wc.x,  Vv.y,  yaib);
        }
        const u64 y1r = sub2(y1ra, y1rb), y1i = add2(y1ia, y1ib);
        const u64 yar = sub2(yara, yarb), yai = sub2(yaia, yaib);
        const u64 ngv = sub2(z, gv.y);
        const u64 nav = sub2(z, av.y);
        fr = fma2(gv.x, y1r, fma2(ngv,  y1i, fr));
        fi = fma2(gv.x, y1i, fma2(gv.y, y1r, fi));
        fr = fma2(av.x, yar, fma2(nav,  yai, fr));
        fi = fma2(av.x, yai, fma2(av.y, yar, fi));
        ++r;
    }

    if (ty > 0)
        sR[ty - 1][tx] = make_ulonglong2(fr, fi);
    __syncthreads();
    if (ty == 0) {
        #pragma unroll
        for (int j = 0; j < SPLIT - 1; ++j) {
            const ulonglong2 rr = sR[j][tx];
            fr = add2(fr, rr.x);  fi = add2(fi, rr.y);
        }
        const int l = base + tx;
        if (l >= NLW && l < SEQ - NLW) {
            const float Psf = exp10f(task[b * 4] * 0.1f) * 0.5f;
            const u64 g2 = pack2(0.01f * Psf);
            const u64 c01 = pack2(0.1f);
            const int gi = b * SEQ + l;
            const ulonglong2 ev = sE[tx + HALO];
            u64 outr = fma2(g2, fr, fma2(c01, g_E1r[gi], ev.x));
            u64 outi = fma2(g2, fi, fma2(c01, g_E1i[gi], ev.y));
            const float2 orr = unpackf2(outr);
            const float2 oii = unpackf2(outi);
            out[b * OUTL + (l - NLW)] = make_float4(orr.x, oii.x, orr.y, oii.y);
        }
    }
}

extern "C" void kernel_launch(void* const* d_in, const int* in_sizes, int n_in,
                              void* d_out, int out_size)
{
    const float2* Er   = (const float2*)d_in[0];
    const float2* Ei   = (const float2*)d_in[1];
    const float*  task = (const float*)d_in[2];
    const float*  w1r  = (const float*)d_in[3];
    const float*  w1i  = (const float*)d_in[4];
    const float*  w2r  = (const float*)d_in[5];
    const float*  w2i  = (const float*)d_in[6];
    const float*  fcr  = (const float*)d_in[7];
    const float*  fci  = (const float*)d_in[8];

    dim3 grid(SEQ / TILE, BATCH);
    dim3 blk(TILE, SPLIT);
    stage1_kernel<<<grid, blk>>>(Er, Ei, task, w1r, w1i, w2r, w2i);
    stage2_kernel<<<grid, blk>>>(Er, Ei, task, fcr, fci, (float4*)d_out);
}